// round 15
// baseline (speedup 1.0000x reference)
#include <cuda_runtime.h>
#include <cuda_fp16.h>
#include <math.h>

#define NNODES 50000
#define FIN    256
#define HH     4
#define HD     64
#define F1     (HH*HD)          // 256
#define EMAX   1600000
#define SLOPE  0.2f
#define FULLM  0xffffffffu

// ---------------- scratch (device globals) ----------------------------------
__device__ __half g_h1h[(size_t)NNODES * F1];    // 25.6 MB (fp16 h1)
__device__ float  g_o1[(size_t)NNODES * F1];     // 51.2 MB
__device__ __half g_h2h[(size_t)NNODES * HD];    // 6.4 MB (fp16 h2)
__device__ float  g_as1[NNODES * HH];
__device__ float  g_ad1[NNODES * HH];
__device__ float  g_as2[NNODES];
__device__ float  g_ad2[NNODES];
__device__ int    g_deg[NNODES];
__device__ int    g_fill[NNODES];
__device__ int    g_roff[NNODES + 1];
__device__ int    g_csr_src[EMAX];               // 6.4 MB

// ---------------- tf32 helpers ----------------------------------------------
__device__ __forceinline__ unsigned f2tf(float f) {
    unsigned u;
    asm("cvt.rna.tf32.f32 %0, %1;" : "=r"(u) : "f"(f));
    return u;
}
__device__ __forceinline__ void mma_tf32(float* c, const unsigned* a, const unsigned* b) {
    asm volatile(
        "mma.sync.aligned.m16n8k8.row.col.f32.tf32.tf32.f32 "
        "{%0,%1,%2,%3}, {%4,%5,%6,%7}, {%8,%9}, {%0,%1,%2,%3};"
        : "+f"(c[0]), "+f"(c[1]), "+f"(c[2]), "+f"(c[3])
        : "r"(a[0]), "r"(a[1]), "r"(a[2]), "r"(a[3]), "r"(b[0]), "r"(b[1]));
}

// ------------- split-tf32 GEMM + fused alpha epilogue (R13 proven core) -----
template<int BM, int BN, int WM, int WN>
__global__ void tf32_gemm_kernel(const float* __restrict__ A,
                                 const float* __restrict__ B,
                                 __half* __restrict__ C16,
                                 const float* __restrict__ a_src,
                                 const float* __restrict__ a_dst,
                                 float* __restrict__ as_out,
                                 float* __restrict__ ad_out,
                                 int M, int N, int K, int heads)
{
    constexpr int BK = 16;
    constexpr int WARPS_M = BM / WM;
    constexpr int WARPS_N = BN / WN;
    constexpr int THREADS = WARPS_M * WARPS_N * 32;
    constexpr int MT = WM / 16;
    constexpr int NT = WN / 8;

    __shared__ unsigned AsH[BM][BK + 4];
    __shared__ unsigned AsL[BM][BK + 4];
    __shared__ unsigned BsH[BK][BN + 8];
    __shared__ unsigned BsL[BK][BN + 8];

    const int tid  = threadIdx.x;
    const int lane = tid & 31;
    const int wid  = tid >> 5;
    const int wm   = wid % WARPS_M;
    const int wn   = wid / WARPS_M;
    const int gid  = lane >> 2;
    const int tg   = lane & 3;
    const int row0 = blockIdx.y * BM;
    const int col0 = blockIdx.x * BN;

    float acc[MT][NT][4];
#pragma unroll
    for (int i = 0; i < MT; i++)
#pragma unroll
        for (int j = 0; j < NT; j++)
#pragma unroll
            for (int r = 0; r < 4; r++) acc[i][j][r] = 0.f;

    for (int k0 = 0; k0 < K; k0 += BK) {
#pragma unroll
        for (int i = tid; i < BM * (BK / 4); i += THREADS) {
            int m  = i / (BK / 4);
            int kq = (i % (BK / 4)) * 4;
            float4 v = make_float4(0.f, 0.f, 0.f, 0.f);
            if (row0 + m < M)
                v = *(const float4*)&A[(size_t)(row0 + m) * K + k0 + kq];
            float f[4] = {v.x, v.y, v.z, v.w};
#pragma unroll
            for (int j = 0; j < 4; j++) {
                unsigned h = f2tf(f[j]);
                AsH[m][kq + j] = h;
                AsL[m][kq + j] = f2tf(f[j] - __uint_as_float(h));
            }
        }
#pragma unroll
        for (int i = tid; i < BK * (BN / 4); i += THREADS) {
            int kk = i / (BN / 4);
            int nq = (i % (BN / 4)) * 4;
            float4 v = *(const float4*)&B[(size_t)(k0 + kk) * N + col0 + nq];
            float f[4] = {v.x, v.y, v.z, v.w};
#pragma unroll
            for (int j = 0; j < 4; j++) {
                unsigned h = f2tf(f[j]);
                BsH[kk][nq + j] = h;
                BsL[kk][nq + j] = f2tf(f[j] - __uint_as_float(h));
            }
        }
        __syncthreads();

#pragma unroll
        for (int ks = 0; ks < BK / 8; ks++) {
            const int kb = ks * 8;
            unsigned aH[MT][4], aL[MT][4], bH[NT][2], bL[NT][2];
#pragma unroll
            for (int mt = 0; mt < MT; mt++) {
                int mr = wm * WM + mt * 16 + gid;
                aH[mt][0] = AsH[mr    ][kb + tg];
                aH[mt][1] = AsH[mr + 8][kb + tg];
                aH[mt][2] = AsH[mr    ][kb + tg + 4];
                aH[mt][3] = AsH[mr + 8][kb + tg + 4];
                aL[mt][0] = AsL[mr    ][kb + tg];
                aL[mt][1] = AsL[mr + 8][kb + tg];
                aL[mt][2] = AsL[mr    ][kb + tg + 4];
                aL[mt][3] = AsL[mr + 8][kb + tg + 4];
            }
#pragma unroll
            for (int nt = 0; nt < NT; nt++) {
                int nc = wn * WN + nt * 8 + gid;
                bH[nt][0] = BsH[kb + tg    ][nc];
                bH[nt][1] = BsH[kb + tg + 4][nc];
                bL[nt][0] = BsL[kb + tg    ][nc];
                bL[nt][1] = BsL[kb + tg + 4][nc];
            }
#pragma unroll
            for (int mt = 0; mt < MT; mt++)
#pragma unroll
                for (int nt = 0; nt < NT; nt++) {
                    mma_tf32(acc[mt][nt], aH[mt], bH[nt]);
                    mma_tf32(acc[mt][nt], aH[mt], bL[nt]);
                    mma_tf32(acc[mt][nt], aL[mt], bH[nt]);
                }
        }
        __syncthreads();
    }

    // ---- epilogue: fp16 store + fused alpha partials ----
    const int head = (col0 + wn * WN) / 64;

#pragma unroll
    for (int mt = 0; mt < MT; mt++) {
        int m0 = row0 + wm * WM + mt * 16 + gid;
        float ps0 = 0.f, pd0 = 0.f, ps1 = 0.f, pd1 = 0.f;
#pragma unroll
        for (int nt = 0; nt < NT; nt++) {
            int nc = col0 + wn * WN + nt * 8 + tg * 2;
            float av0 = a_src[head * 64 + ((nc    ) & 63)];
            float av1 = a_src[head * 64 + ((nc + 1) & 63)];
            float dv0 = a_dst[head * 64 + ((nc    ) & 63)];
            float dv1 = a_dst[head * 64 + ((nc + 1) & 63)];
            ps0 = fmaf(acc[mt][nt][0], av0, fmaf(acc[mt][nt][1], av1, ps0));
            pd0 = fmaf(acc[mt][nt][0], dv0, fmaf(acc[mt][nt][1], dv1, pd0));
            ps1 = fmaf(acc[mt][nt][2], av0, fmaf(acc[mt][nt][3], av1, ps1));
            pd1 = fmaf(acc[mt][nt][2], dv0, fmaf(acc[mt][nt][3], dv1, pd1));
            if (m0 < M)
                *(__half2*)&C16[(size_t)m0 * N + nc] =
                    __floats2half2_rn(acc[mt][nt][0], acc[mt][nt][1]);
            if (m0 + 8 < M)
                *(__half2*)&C16[(size_t)(m0 + 8) * N + nc] =
                    __floats2half2_rn(acc[mt][nt][2], acc[mt][nt][3]);
        }
#pragma unroll
        for (int o = 1; o < 4; o <<= 1) {
            ps0 += __shfl_xor_sync(FULLM, ps0, o);
            pd0 += __shfl_xor_sync(FULLM, pd0, o);
            ps1 += __shfl_xor_sync(FULLM, ps1, o);
            pd1 += __shfl_xor_sync(FULLM, pd1, o);
        }
        if (tg == 0) {
            if (m0 < M) {
                atomicAdd(&as_out[(size_t)m0 * heads + head], ps0);
                atomicAdd(&ad_out[(size_t)m0 * heads + head], pd0);
            }
            if (m0 + 8 < M) {
                atomicAdd(&as_out[(size_t)(m0 + 8) * heads + head], ps1);
                atomicAdd(&ad_out[(size_t)(m0 + 8) * heads + head], pd1);
            }
        }
    }
}

// ---------------- CSR build -------------------------------------------------
__global__ void hist_kernel(const int* __restrict__ dst, int E, int* __restrict__ deg)
{
    int e = blockIdx.x * blockDim.x + threadIdx.x;
    if (e >= E) return;
    int d = dst[e];
    if ((unsigned)d < NNODES) atomicAdd(&deg[d], 1);
}

__global__ void scan_kernel(const int* __restrict__ deg, int* __restrict__ roff)
{
    __shared__ int part[1024];
    const int tid = threadIdx.x;
    const int CH = (NNODES + 1023) / 1024;
    const int base = tid * CH;
    int s = 0;
    for (int i = 0; i < CH; i++) {
        int idx = base + i;
        if (idx < NNODES) s += deg[idx];
    }
    part[tid] = s;
    __syncthreads();
    for (int off = 1; off < 1024; off <<= 1) {
        int v = 0;
        if (tid >= off) v = part[tid - off];
        __syncthreads();
        if (tid >= off) part[tid] += v;
        __syncthreads();
    }
    int run = (tid == 0) ? 0 : part[tid - 1];
    for (int i = 0; i < CH; i++) {
        int idx = base + i;
        if (idx < NNODES) { roff[idx] = run; run += deg[idx]; }
    }
    if (tid == 1023) roff[NNODES] = run;
}

__global__ void scatter_kernel(const int* __restrict__ src, const int* __restrict__ dst,
                               int E, const int* __restrict__ roff,
                               int* __restrict__ fill, int* __restrict__ csr)
{
    int e = blockIdx.x * blockDim.x + threadIdx.x;
    if (e >= E) return;
    int d = dst[e], s = src[e];
    if ((unsigned)d >= NNODES || (unsigned)s >= NNODES) return;
    int p = atomicAdd(&fill[d], 1);
    csr[roff[d] + p] = s;
}

__device__ __forceinline__ float lexp(float e) {
    e = e > 0.f ? e : SLOPE * e;
    return __expf(e);
}

// -------- layer-1 single-pass softmax+gather: 8-wide MLP unroll -------------
__global__ void gather1_kernel(const int* __restrict__ roff,
                               const int* __restrict__ csr,
                               const float* __restrict__ as_in,
                               const float* __restrict__ ad_in,
                               const __half* __restrict__ h16,
                               const float* __restrict__ bias,
                               float* __restrict__ out)
{
    int warp = (blockIdx.x * blockDim.x + threadIdx.x) >> 5;
    int lane = threadIdx.x & 31;
    if (warp >= NNODES) return;
    const int d = warp;
    const int beg = roff[d], end = roff[d + 1];
    const int hidx = lane >> 3;          // 8 lanes per head

    float4 ad4 = *(const float4*)(ad_in + (size_t)d * 4);

    float acc[8];
#pragma unroll
    for (int k = 0; k < 8; k++) acc[k] = 0.f;
    float4 ws = make_float4(0.f, 0.f, 0.f, 0.f);

#define ACCUM1(w, q)                                                    \
    {                                                                   \
        const __half2* hp = (const __half2*)&(q);                       \
        float2 f0 = __half22float2(hp[0]);                              \
        float2 f1 = __half22float2(hp[1]);                              \
        float2 f2 = __half22float2(hp[2]);                              \
        float2 f3 = __half22float2(hp[3]);                              \
        acc[0] = fmaf(w, f0.x, acc[0]); acc[1] = fmaf(w, f0.y, acc[1]); \
        acc[2] = fmaf(w, f1.x, acc[2]); acc[3] = fmaf(w, f1.y, acc[3]); \
        acc[4] = fmaf(w, f2.x, acc[4]); acc[5] = fmaf(w, f2.y, acc[5]); \
        acc[6] = fmaf(w, f3.x, acc[6]); acc[7] = fmaf(w, f3.y, acc[7]); \
    }
#define SELW(wx, wy, wz, ww) \
    ((hidx == 0) ? (wx) : (hidx == 1) ? (wy) : (hidx == 2) ? (wz) : (ww))
#define BCASTW(dstw, t)                                                 \
    {                                                                   \
        float _bx = __shfl_sync(FULLM, w4.x, (t));                      \
        float _by = __shfl_sync(FULLM, w4.y, (t));                      \
        float _bz = __shfl_sync(FULLM, w4.z, (t));                      \
        float _bw = __shfl_sync(FULLM, w4.w, (t));                      \
        dstw = SELW(_bx, _by, _bz, _bw);                                \
    }

    for (int j0 = beg; j0 < end; j0 += 32) {
        int cnt = min(32, end - j0);
        int my = 0;
        float4 w4 = make_float4(0.f, 0.f, 0.f, 0.f);
        if (lane < cnt) {
            my = csr[j0 + lane];
            float4 a = *(const float4*)(as_in + (size_t)my * 4);
            w4.x = lexp(a.x + ad4.x);
            w4.y = lexp(a.y + ad4.y);
            w4.z = lexp(a.z + ad4.z);
            w4.w = lexp(a.w + ad4.w);
            ws.x += w4.x; ws.y += w4.y; ws.z += w4.z; ws.w += w4.w;
        }
        int t = 0;
        for (; t + 7 < cnt; t += 8) {
            int s[8];
            uint4 q[8];
            float w[8];
#pragma unroll
            for (int u = 0; u < 8; u++)
                s[u] = __shfl_sync(FULLM, my, t + u);
#pragma unroll
            for (int u = 0; u < 8; u++)
                q[u] = *(const uint4*)(h16 + (size_t)s[u] * F1 + lane * 8);
#pragma unroll
            for (int u = 0; u < 8; u++)
                BCASTW(w[u], t + u);
#pragma unroll
            for (int u = 0; u < 8; u++)
                ACCUM1(w[u], q[u]);
        }
        for (; t < cnt; t++) {
            int s0 = __shfl_sync(FULLM, my, t);
            uint4 q0 = *(const uint4*)(h16 + (size_t)s0 * F1 + lane * 8);
            float w0;
            BCASTW(w0, t);
            ACCUM1(w0, q0);
        }
    }
    {   // self loop
        float4 a = *(const float4*)(as_in + (size_t)d * 4);
        float sx = lexp(a.x + ad4.x), sy = lexp(a.y + ad4.y);
        float sz = lexp(a.z + ad4.z), sw = lexp(a.w + ad4.w);
        if (lane == 0) { ws.x += sx; ws.y += sy; ws.z += sz; ws.w += sw; }
        float w0 = SELW(sx, sy, sz, sw);
        uint4 q0 = *(const uint4*)(h16 + (size_t)d * F1 + lane * 8);
        ACCUM1(w0, q0);
    }
#undef ACCUM1
#undef BCASTW

#pragma unroll
    for (int o = 16; o > 0; o >>= 1) {
        ws.x += __shfl_xor_sync(FULLM, ws.x, o);
        ws.y += __shfl_xor_sync(FULLM, ws.y, o);
        ws.z += __shfl_xor_sync(FULLM, ws.z, o);
        ws.w += __shfl_xor_sync(FULLM, ws.w, o);
    }
    float inv = 1.f / (SELW(ws.x, ws.y, ws.z, ws.w) + 1e-16f);
#undef SELW

    size_t base = (size_t)d * F1 + lane * 8;
#pragma unroll
    for (int k = 0; k < 8; k++) {
        float v = acc[k] * inv + bias[lane * 8 + k];
        out[base + k] = v > 0.f ? v : expm1f(v);
    }
}

// -------- layer-2 single-pass softmax+gather: 8-wide MLP unroll --------------
__global__ void gather2_kernel(const int* __restrict__ roff,
                               const int* __restrict__ csr,
                               const float* __restrict__ as_in,
                               const float* __restrict__ ad_in,
                               const __half* __restrict__ h16,
                               const float* __restrict__ bias,
                               float* __restrict__ out)
{
    int warp = (blockIdx.x * blockDim.x + threadIdx.x) >> 5;
    int lane = threadIdx.x & 31;
    if (warp >= NNODES) return;
    const int d = warp;
    const int beg = roff[d], end = roff[d + 1];

    float add = ad_in[d];
    float ws = 0.f;
    float2 acc = make_float2(0.f, 0.f);

    for (int j0 = beg; j0 < end; j0 += 32) {
        int cnt = min(32, end - j0);
        int my = 0;
        float wmy = 0.f;
        if (lane < cnt) {
            my = csr[j0 + lane];
            wmy = lexp(as_in[my] + add);
            ws += wmy;
        }
        int t = 0;
        for (; t + 7 < cnt; t += 8) {
            int s[8];
            __half2 v[8];
            float w[8];
#pragma unroll
            for (int u = 0; u < 8; u++)
                s[u] = __shfl_sync(FULLM, my, t + u);
#pragma unroll
            for (int u = 0; u < 8; u++)
                v[u] = *(const __half2*)(h16 + (size_t)s[u] * HD + lane * 2);
#pragma unroll
            for (int u = 0; u < 8; u++)
                w[u] = __shfl_sync(FULLM, wmy, t + u);
#pragma unroll
            for (int u = 0; u < 8; u++) {
                float2 f = __half22float2(v[u]);
                acc.x = fmaf(w[u], f.x, acc.x);
                acc.y = fmaf(w[u], f.y, acc.y);
            }
        }
        for (; t < cnt; t++) {
            int s0 = __shfl_sync(FULLM, my, t);
            float w0 = __shfl_sync(FULLM, wmy, t);
            float2 u = __half22float2(*(const __half2*)(h16 + (size_t)s0 * HD + lane * 2));
            acc.x = fmaf(w0, u.x, acc.x); acc.y = fmaf(w0, u.y, acc.y);
        }
    }
    {   // self loop
        float w0 = lexp(as_in[d] + add);
        if (lane == 0) ws += w0;
        float2 u = __half22float2(*(const __half2*)(h16 + (size_t)d * HD + lane * 2));
        acc.x = fmaf(w0, u.x, acc.x); acc.y = fmaf(w0, u.y, acc.y);
    }

#pragma unroll
    for (int o = 16; o > 0; o >>= 1) ws += __shfl_xor_sync(FULLM, ws, o);
    float inv = 1.f / (ws + 1e-16f);

    out[(size_t)d * HD + lane * 2 + 0] = acc.x * inv + bias[lane * 2 + 0];
    out[(size_t)d * HD + lane * 2 + 1] = acc.y * inv + bias[lane * 2 + 1];
}

// ---------------- launch ----------------------------------------------------
extern "C" void kernel_launch(void* const* d_in, const int* in_sizes, int n_in,
                              void* d_out, int out_size)
{
    const float* x     = (const float*)d_in[0];
    const int*   ei    = (const int*)d_in[1];     // int32 (JAX x64 disabled)
    const float* W1    = (const float*)d_in[2];
    const float* asrc1 = (const float*)d_in[3];
    const float* adst1 = (const float*)d_in[4];
    const float* b1    = (const float*)d_in[5];
    const float* W2    = (const float*)d_in[6];
    const float* asrc2 = (const float*)d_in[7];
    const float* adst2 = (const float*)d_in[8];
    const float* b2    = (const float*)d_in[9];
    float*       out   = (float*)d_out;

    int E = in_sizes[1] / 2;
    if (E > EMAX) E = EMAX;
    const int* src = ei;
    const int* dst = ei + E;

    float *o1, *as1, *ad1, *as2, *ad2;
    __half *h1h, *h2h;
    int *deg, *fill, *roff, *csr;
    cudaGetSymbolAddress((void**)&h1h,  g_h1h);
    cudaGetSymbolAddress((void**)&o1,   g_o1);
    cudaGetSymbolAddress((void**)&h2h,  g_h2h);
    cudaGetSymbolAddress((void**)&as1,  g_as1);
    cudaGetSymbolAddress((void**)&ad1,  g_ad1);
    cudaGetSymbolAddress((void**)&as2,  g_as2);
    cudaGetSymbolAddress((void**)&ad2,  g_ad2);
    cudaGetSymbolAddress((void**)&deg,  g_deg);
    cudaGetSymbolAddress((void**)&fill, g_fill);
    cudaGetSymbolAddress((void**)&roff, g_roff);
    cudaGetSymbolAddress((void**)&csr,  g_csr_src);

    cudaMemsetAsync(as1, 0, (size_t)NNODES * HH * sizeof(float));
    cudaMemsetAsync(ad1, 0, (size_t)NNODES * HH * sizeof(float));
    cudaMemsetAsync(as2, 0, (size_t)NNODES * sizeof(float));
    cudaMemsetAsync(ad2, 0, (size_t)NNODES * sizeof(float));
    cudaMemsetAsync(deg,  0, NNODES * sizeof(int));
    cudaMemsetAsync(fill, 0, NNODES * sizeof(int));

    hist_kernel<<<(E + 255) / 256, 256>>>(dst, E, deg);
    scan_kernel<<<1, 1024>>>(deg, roff);
    scatter_kernel<<<(E + 255) / 256, 256>>>(src, dst, E, roff, fill, csr);

    // ---- layer 1 ----
    {
        dim3 grid(F1 / 128, (NNODES + 127) / 128);
        tf32_gemm_kernel<128, 128, 64, 32><<<grid, 256>>>(
            x, W1, h1h, asrc1, adst1, as1, ad1, NNODES, F1, FIN, HH);
    }
    gather1_kernel<<<(NNODES + 7) / 8, 256>>>(roff, csr, as1, ad1, h1h, b1, o1);

    // ---- layer 2 ----
    {
        dim3 grid(1, (NNODES + 127) / 128);
        tf32_gemm_kernel<128, 64, 64, 16><<<grid, 256>>>(
            o1, W2, h2h, asrc2, adst2, as2, ad2, NNODES, HD, F1, 1);
    }
    gather2_kernel<<<(NNODES + 7) / 8, 256>>>(roff, csr, as2, ad2, h2h, b2, out);
}

// round 16
// speedup vs baseline: 1.1397x; 1.1397x over previous
#include <cuda_runtime.h>
#include <cuda_fp16.h>
#include <math.h>

#define NNODES 50000
#define FIN    256
#define HH     4
#define HD     64
#define F1     (HH*HD)          // 256
#define EMAX   1600000
#define SLOPE  0.2f
#define FULLM  0xffffffffu

// ---------------- scratch (device globals) ----------------------------------
__device__ __half g_h1h[(size_t)NNODES * F1];    // 25.6 MB (fp16 h1)
__device__ float  g_o1[(size_t)NNODES * F1];     // 51.2 MB
__device__ __half g_h2h[(size_t)NNODES * HD];    // 6.4 MB (fp16 h2)
__device__ float  g_as1[NNODES * HH];
__device__ float  g_ad1[NNODES * HH];
__device__ float  g_as2[NNODES];
__device__ float  g_ad2[NNODES];
__device__ int    g_deg[NNODES];
__device__ int    g_roff[NNODES + 1];
__device__ int    g_csr_src[EMAX];               // 6.4 MB

// ---------------- tf32 helpers ----------------------------------------------
__device__ __forceinline__ unsigned f2tf(float f) {
    unsigned u;
    asm("cvt.rna.tf32.f32 %0, %1;" : "=r"(u) : "f"(f));
    return u;
}
__device__ __forceinline__ void mma_tf32(float* c, const unsigned* a, const unsigned* b) {
    asm volatile(
        "mma.sync.aligned.m16n8k8.row.col.f32.tf32.tf32.f32 "
        "{%0,%1,%2,%3}, {%4,%5,%6,%7}, {%8,%9}, {%0,%1,%2,%3};"
        : "+f"(c[0]), "+f"(c[1]), "+f"(c[2]), "+f"(c[3])
        : "r"(a[0]), "r"(a[1]), "r"(a[2]), "r"(a[3]), "r"(b[0]), "r"(b[1]));
}

// ------------- split-tf32 GEMM + fused alpha epilogue (R13 proven core) -----
template<int BM, int BN, int WM, int WN>
__global__ void tf32_gemm_kernel(const float* __restrict__ A,
                                 const float* __restrict__ B,
                                 __half* __restrict__ C16,
                                 const float* __restrict__ a_src,
                                 const float* __restrict__ a_dst,
                                 float* __restrict__ as_out,
                                 float* __restrict__ ad_out,
                                 int M, int N, int K, int heads)
{
    constexpr int BK = 16;
    constexpr int WARPS_M = BM / WM;
    constexpr int WARPS_N = BN / WN;
    constexpr int THREADS = WARPS_M * WARPS_N * 32;
    constexpr int MT = WM / 16;
    constexpr int NT = WN / 8;

    __shared__ unsigned AsH[BM][BK + 4];
    __shared__ unsigned AsL[BM][BK + 4];
    __shared__ unsigned BsH[BK][BN + 8];
    __shared__ unsigned BsL[BK][BN + 8];

    const int tid  = threadIdx.x;
    const int lane = tid & 31;
    const int wid  = tid >> 5;
    const int wm   = wid % WARPS_M;
    const int wn   = wid / WARPS_M;
    const int gid  = lane >> 2;
    const int tg   = lane & 3;
    const int row0 = blockIdx.y * BM;
    const int col0 = blockIdx.x * BN;

    float acc[MT][NT][4];
#pragma unroll
    for (int i = 0; i < MT; i++)
#pragma unroll
        for (int j = 0; j < NT; j++)
#pragma unroll
            for (int r = 0; r < 4; r++) acc[i][j][r] = 0.f;

    for (int k0 = 0; k0 < K; k0 += BK) {
#pragma unroll
        for (int i = tid; i < BM * (BK / 4); i += THREADS) {
            int m  = i / (BK / 4);
            int kq = (i % (BK / 4)) * 4;
            float4 v = make_float4(0.f, 0.f, 0.f, 0.f);
            if (row0 + m < M)
                v = *(const float4*)&A[(size_t)(row0 + m) * K + k0 + kq];
            float f[4] = {v.x, v.y, v.z, v.w};
#pragma unroll
            for (int j = 0; j < 4; j++) {
                unsigned h = f2tf(f[j]);
                AsH[m][kq + j] = h;
                AsL[m][kq + j] = f2tf(f[j] - __uint_as_float(h));
            }
        }
#pragma unroll
        for (int i = tid; i < BK * (BN / 4); i += THREADS) {
            int kk = i / (BN / 4);
            int nq = (i % (BN / 4)) * 4;
            float4 v = *(const float4*)&B[(size_t)(k0 + kk) * N + col0 + nq];
            float f[4] = {v.x, v.y, v.z, v.w};
#pragma unroll
            for (int j = 0; j < 4; j++) {
                unsigned h = f2tf(f[j]);
                BsH[kk][nq + j] = h;
                BsL[kk][nq + j] = f2tf(f[j] - __uint_as_float(h));
            }
        }
        __syncthreads();

#pragma unroll
        for (int ks = 0; ks < BK / 8; ks++) {
            const int kb = ks * 8;
            unsigned aH[MT][4], aL[MT][4], bH[NT][2], bL[NT][2];
#pragma unroll
            for (int mt = 0; mt < MT; mt++) {
                int mr = wm * WM + mt * 16 + gid;
                aH[mt][0] = AsH[mr    ][kb + tg];
                aH[mt][1] = AsH[mr + 8][kb + tg];
                aH[mt][2] = AsH[mr    ][kb + tg + 4];
                aH[mt][3] = AsH[mr + 8][kb + tg + 4];
                aL[mt][0] = AsL[mr    ][kb + tg];
                aL[mt][1] = AsL[mr + 8][kb + tg];
                aL[mt][2] = AsL[mr    ][kb + tg + 4];
                aL[mt][3] = AsL[mr + 8][kb + tg + 4];
            }
#pragma unroll
            for (int nt = 0; nt < NT; nt++) {
                int nc = wn * WN + nt * 8 + gid;
                bH[nt][0] = BsH[kb + tg    ][nc];
                bH[nt][1] = BsH[kb + tg + 4][nc];
                bL[nt][0] = BsL[kb + tg    ][nc];
                bL[nt][1] = BsL[kb + tg + 4][nc];
            }
#pragma unroll
            for (int mt = 0; mt < MT; mt++)
#pragma unroll
                for (int nt = 0; nt < NT; nt++) {
                    mma_tf32(acc[mt][nt], aH[mt], bH[nt]);
                    mma_tf32(acc[mt][nt], aH[mt], bL[nt]);
                    mma_tf32(acc[mt][nt], aL[mt], bH[nt]);
                }
        }
        __syncthreads();
    }

    // ---- epilogue: fp16 store + fused alpha partials ----
    const int head = (col0 + wn * WN) / 64;

#pragma unroll
    for (int mt = 0; mt < MT; mt++) {
        int m0 = row0 + wm * WM + mt * 16 + gid;
        float ps0 = 0.f, pd0 = 0.f, ps1 = 0.f, pd1 = 0.f;
#pragma unroll
        for (int nt = 0; nt < NT; nt++) {
            int nc = col0 + wn * WN + nt * 8 + tg * 2;
            float av0 = a_src[head * 64 + ((nc    ) & 63)];
            float av1 = a_src[head * 64 + ((nc + 1) & 63)];
            float dv0 = a_dst[head * 64 + ((nc    ) & 63)];
            float dv1 = a_dst[head * 64 + ((nc + 1) & 63)];
            ps0 = fmaf(acc[mt][nt][0], av0, fmaf(acc[mt][nt][1], av1, ps0));
            pd0 = fmaf(acc[mt][nt][0], dv0, fmaf(acc[mt][nt][1], dv1, pd0));
            ps1 = fmaf(acc[mt][nt][2], av0, fmaf(acc[mt][nt][3], av1, ps1));
            pd1 = fmaf(acc[mt][nt][2], dv0, fmaf(acc[mt][nt][3], dv1, pd1));
            if (m0 < M)
                *(__half2*)&C16[(size_t)m0 * N + nc] =
                    __floats2half2_rn(acc[mt][nt][0], acc[mt][nt][1]);
            if (m0 + 8 < M)
                *(__half2*)&C16[(size_t)(m0 + 8) * N + nc] =
                    __floats2half2_rn(acc[mt][nt][2], acc[mt][nt][3]);
        }
#pragma unroll
        for (int o = 1; o < 4; o <<= 1) {
            ps0 += __shfl_xor_sync(FULLM, ps0, o);
            pd0 += __shfl_xor_sync(FULLM, pd0, o);
            ps1 += __shfl_xor_sync(FULLM, ps1, o);
            pd1 += __shfl_xor_sync(FULLM, pd1, o);
        }
        if (tg == 0) {
            if (m0 < M) {
                atomicAdd(&as_out[(size_t)m0 * heads + head], ps0);
                atomicAdd(&ad_out[(size_t)m0 * heads + head], pd0);
            }
            if (m0 + 8 < M) {
                atomicAdd(&as_out[(size_t)(m0 + 8) * heads + head], ps1);
                atomicAdd(&ad_out[(size_t)(m0 + 8) * heads + head], pd1);
            }
        }
    }
}

// ---------------- CSR build -------------------------------------------------
__global__ void hist_kernel(const int* __restrict__ dst, int E, int* __restrict__ deg)
{
    int e = blockIdx.x * blockDim.x + threadIdx.x;
    if (e >= E) return;
    int d = dst[e];
    if ((unsigned)d < NNODES) atomicAdd(&deg[d], 1);
}

__global__ void scan_kernel(const int* __restrict__ deg, int* __restrict__ roff)
{
    __shared__ int part[1024];
    const int tid = threadIdx.x;
    const int CH = (NNODES + 1023) / 1024;
    const int base = tid * CH;
    int s = 0;
    for (int i = 0; i < CH; i++) {
        int idx = base + i;
        if (idx < NNODES) s += deg[idx];
    }
    part[tid] = s;
    __syncthreads();
    for (int off = 1; off < 1024; off <<= 1) {
        int v = 0;
        if (tid >= off) v = part[tid - off];
        __syncthreads();
        if (tid >= off) part[tid] += v;
        __syncthreads();
    }
    int run = (tid == 0) ? 0 : part[tid - 1];
    for (int i = 0; i < CH; i++) {
        int idx = base + i;
        if (idx < NNODES) { roff[idx] = run; run += deg[idx]; }
    }
    if (tid == 1023) roff[NNODES] = run;
}

// Reuses deg as the per-node slot counter (counts down to 0); no fill array.
__global__ void scatter_kernel(const int* __restrict__ src, const int* __restrict__ dst,
                               int E, const int* __restrict__ roff,
                               int* __restrict__ deg, int* __restrict__ csr)
{
    int e = blockIdx.x * blockDim.x + threadIdx.x;
    if (e >= E) return;
    int d = dst[e], s = src[e];
    if ((unsigned)d >= NNODES || (unsigned)s >= NNODES) return;
    int old = atomicSub(&deg[d], 1);          // old in [1, deg]
    csr[roff[d] + old - 1] = s;
}

__device__ __forceinline__ float lexp(float e) {
    e = e > 0.f ? e : SLOPE * e;
    return __expf(e);
}

// -------- layer-1 single-pass softmax+gather (R13 proven, 4-wide) -----------
__global__ void gather1_kernel(const int* __restrict__ roff,
                               const int* __restrict__ csr,
                               const float* __restrict__ as_in,
                               const float* __restrict__ ad_in,
                               const __half* __restrict__ h16,
                               const float* __restrict__ bias,
                               float* __restrict__ out)
{
    int warp = (blockIdx.x * blockDim.x + threadIdx.x) >> 5;
    int lane = threadIdx.x & 31;
    if (warp >= NNODES) return;
    const int d = warp;
    const int beg = roff[d], end = roff[d + 1];
    const int hidx = lane >> 3;          // 8 lanes per head

    float4 ad4 = *(const float4*)(ad_in + (size_t)d * 4);

    float acc[8];
#pragma unroll
    for (int k = 0; k < 8; k++) acc[k] = 0.f;
    float4 ws = make_float4(0.f, 0.f, 0.f, 0.f);

#define ACCUM1(w, q)                                                    \
    {                                                                   \
        const __half2* hp = (const __half2*)&(q);                       \
        float2 f0 = __half22float2(hp[0]);                              \
        float2 f1 = __half22float2(hp[1]);                              \
        float2 f2 = __half22float2(hp[2]);                              \
        float2 f3 = __half22float2(hp[3]);                              \
        acc[0] = fmaf(w, f0.x, acc[0]); acc[1] = fmaf(w, f0.y, acc[1]); \
        acc[2] = fmaf(w, f1.x, acc[2]); acc[3] = fmaf(w, f1.y, acc[3]); \
        acc[4] = fmaf(w, f2.x, acc[4]); acc[5] = fmaf(w, f2.y, acc[5]); \
        acc[6] = fmaf(w, f3.x, acc[6]); acc[7] = fmaf(w, f3.y, acc[7]); \
    }
#define SELW(wx, wy, wz, ww) \
    ((hidx == 0) ? (wx) : (hidx == 1) ? (wy) : (hidx == 2) ? (wz) : (ww))
#define BCASTW(dstw, t)                                                 \
    {                                                                   \
        float _bx = __shfl_sync(FULLM, w4.x, (t));                      \
        float _by = __shfl_sync(FULLM, w4.y, (t));                      \
        float _bz = __shfl_sync(FULLM, w4.z, (t));                      \
        float _bw = __shfl_sync(FULLM, w4.w, (t));                      \
        dstw = SELW(_bx, _by, _bz, _bw);                                \
    }

    for (int j0 = beg; j0 < end; j0 += 32) {
        int cnt = min(32, end - j0);
        int my = 0;
        float4 w4 = make_float4(0.f, 0.f, 0.f, 0.f);
        if (lane < cnt) {
            my = csr[j0 + lane];
            float4 a = *(const float4*)(as_in + (size_t)my * 4);
            w4.x = lexp(a.x + ad4.x);
            w4.y = lexp(a.y + ad4.y);
            w4.z = lexp(a.z + ad4.z);
            w4.w = lexp(a.w + ad4.w);
            ws.x += w4.x; ws.y += w4.y; ws.z += w4.z; ws.w += w4.w;
        }
        int t = 0;
        for (; t + 3 < cnt; t += 4) {
            int s0 = __shfl_sync(FULLM, my, t);
            int s1 = __shfl_sync(FULLM, my, t + 1);
            int s2 = __shfl_sync(FULLM, my, t + 2);
            int s3 = __shfl_sync(FULLM, my, t + 3);
            uint4 q0 = *(const uint4*)(h16 + (size_t)s0 * F1 + lane * 8);
            uint4 q1 = *(const uint4*)(h16 + (size_t)s1 * F1 + lane * 8);
            uint4 q2 = *(const uint4*)(h16 + (size_t)s2 * F1 + lane * 8);
            uint4 q3 = *(const uint4*)(h16 + (size_t)s3 * F1 + lane * 8);
            float w0, w1, w2, w3;
            BCASTW(w0, t);
            BCASTW(w1, t + 1);
            BCASTW(w2, t + 2);
            BCASTW(w3, t + 3);
            ACCUM1(w0, q0); ACCUM1(w1, q1); ACCUM1(w2, q2); ACCUM1(w3, q3);
        }
        for (; t < cnt; t++) {
            int s0 = __shfl_sync(FULLM, my, t);
            uint4 q0 = *(const uint4*)(h16 + (size_t)s0 * F1 + lane * 8);
            float w0;
            BCASTW(w0, t);
            ACCUM1(w0, q0);
        }
    }
    {   // self loop
        float4 a = *(const float4*)(as_in + (size_t)d * 4);
        float sx = lexp(a.x + ad4.x), sy = lexp(a.y + ad4.y);
        float sz = lexp(a.z + ad4.z), sw = lexp(a.w + ad4.w);
        if (lane == 0) { ws.x += sx; ws.y += sy; ws.z += sz; ws.w += sw; }
        float w0 = SELW(sx, sy, sz, sw);
        uint4 q0 = *(const uint4*)(h16 + (size_t)d * F1 + lane * 8);
        ACCUM1(w0, q0);
    }
#undef ACCUM1
#undef BCASTW

#pragma unroll
    for (int o = 16; o > 0; o >>= 1) {
        ws.x += __shfl_xor_sync(FULLM, ws.x, o);
        ws.y += __shfl_xor_sync(FULLM, ws.y, o);
        ws.z += __shfl_xor_sync(FULLM, ws.z, o);
        ws.w += __shfl_xor_sync(FULLM, ws.w, o);
    }
    float inv = 1.f / (SELW(ws.x, ws.y, ws.z, ws.w) + 1e-16f);
#undef SELW

    size_t base = (size_t)d * F1 + lane * 8;
#pragma unroll
    for (int k = 0; k < 8; k++) {
        float v = acc[k] * inv + bias[lane * 8 + k];
        out[base + k] = v > 0.f ? v : expm1f(v);
    }
}

// -------- layer-2 single-pass softmax+gather (R13 proven, 4-wide) -----------
__global__ void gather2_kernel(const int* __restrict__ roff,
                               const int* __restrict__ csr,
                               const float* __restrict__ as_in,
                               const float* __restrict__ ad_in,
                               const __half* __restrict__ h16,
                               const float* __restrict__ bias,
                               float* __restrict__ out)
{
    int warp = (blockIdx.x * blockDim.x + threadIdx.x) >> 5;
    int lane = threadIdx.x & 31;
    if (warp >= NNODES) return;
    const int d = warp;
    const int beg = roff[d], end = roff[d + 1];

    float add = ad_in[d];
    float ws = 0.f;
    float2 acc = make_float2(0.f, 0.f);

    for (int j0 = beg; j0 < end; j0 += 32) {
        int cnt = min(32, end - j0);
        int my = 0;
        float wmy = 0.f;
        if (lane < cnt) {
            my = csr[j0 + lane];
            wmy = lexp(as_in[my] + add);
            ws += wmy;
        }
        int t = 0;
        for (; t + 3 < cnt; t += 4) {
            int s0 = __shfl_sync(FULLM, my, t);
            int s1 = __shfl_sync(FULLM, my, t + 1);
            int s2 = __shfl_sync(FULLM, my, t + 2);
            int s3 = __shfl_sync(FULLM, my, t + 3);
            __half2 v0 = *(const __half2*)(h16 + (size_t)s0 * HD + lane * 2);
            __half2 v1 = *(const __half2*)(h16 + (size_t)s1 * HD + lane * 2);
            __half2 v2 = *(const __half2*)(h16 + (size_t)s2 * HD + lane * 2);
            __half2 v3 = *(const __half2*)(h16 + (size_t)s3 * HD + lane * 2);
            float w0 = __shfl_sync(FULLM, wmy, t);
            float w1 = __shfl_sync(FULLM, wmy, t + 1);
            float w2 = __shfl_sync(FULLM, wmy, t + 2);
            float w3 = __shfl_sync(FULLM, wmy, t + 3);
            float2 f0 = __half22float2(v0), f1 = __half22float2(v1);
            float2 f2 = __half22float2(v2), f3 = __half22float2(v3);
            acc.x = fmaf(w0, f0.x, acc.x); acc.y = fmaf(w0, f0.y, acc.y);
            acc.x = fmaf(w1, f1.x, acc.x); acc.y = fmaf(w1, f1.y, acc.y);
            acc.x = fmaf(w2, f2.x, acc.x); acc.y = fmaf(w2, f2.y, acc.y);
            acc.x = fmaf(w3, f3.x, acc.x); acc.y = fmaf(w3, f3.y, acc.y);
        }
        for (; t < cnt; t++) {
            int s0 = __shfl_sync(FULLM, my, t);
            float w0 = __shfl_sync(FULLM, wmy, t);
            float2 u = __half22float2(*(const __half2*)(h16 + (size_t)s0 * HD + lane * 2));
            acc.x = fmaf(w0, u.x, acc.x); acc.y = fmaf(w0, u.y, acc.y);
        }
    }
    {   // self loop
        float w0 = lexp(as_in[d] + add);
        if (lane == 0) ws += w0;
        float2 u = __half22float2(*(const __half2*)(h16 + (size_t)d * HD + lane * 2));
        acc.x = fmaf(w0, u.x, acc.x); acc.y = fmaf(w0, u.y, acc.y);
    }

#pragma unroll
    for (int o = 16; o > 0; o >>= 1) ws += __shfl_xor_sync(FULLM, ws, o);
    float inv = 1.f / (ws + 1e-16f);

    out[(size_t)d * HD + lane * 2 + 0] = acc.x * inv + bias[lane * 2 + 0];
    out[(size_t)d * HD + lane * 2 + 1] = acc.y * inv + bias[lane * 2 + 1];
}

// ---------------- launch ----------------------------------------------------
extern "C" void kernel_launch(void* const* d_in, const int* in_sizes, int n_in,
                              void* d_out, int out_size)
{
    const float* x     = (const float*)d_in[0];
    const int*   ei    = (const int*)d_in[1];     // int32 (JAX x64 disabled)
    const float* W1    = (const float*)d_in[2];
    const float* asrc1 = (const float*)d_in[3];
    const float* adst1 = (const float*)d_in[4];
    const float* b1    = (const float*)d_in[5];
    const float* W2    = (const float*)d_in[6];
    const float* asrc2 = (const float*)d_in[7];
    const float* adst2 = (const float*)d_in[8];
    const float* b2    = (const float*)d_in[9];
    float*       out   = (float*)d_out;

    int E = in_sizes[1] / 2;
    if (E > EMAX) E = EMAX;
    const int* src = ei;
    const int* dst = ei + E;

    float *o1, *as1, *ad1, *as2, *ad2;
    __half *h1h, *h2h;
    int *deg, *roff, *csr;
    cudaGetSymbolAddress((void**)&h1h,  g_h1h);
    cudaGetSymbolAddress((void**)&o1,   g_o1);
    cudaGetSymbolAddress((void**)&h2h,  g_h2h);
    cudaGetSymbolAddress((void**)&as1,  g_as1);
    cudaGetSymbolAddress((void**)&ad1,  g_ad1);
    cudaGetSymbolAddress((void**)&as2,  g_as2);
    cudaGetSymbolAddress((void**)&ad2,  g_ad2);
    cudaGetSymbolAddress((void**)&deg,  g_deg);
    cudaGetSymbolAddress((void**)&roff, g_roff);
    cudaGetSymbolAddress((void**)&csr,  g_csr_src);

    cudaMemsetAsync(as1, 0, (size_t)NNODES * HH * sizeof(float));
    cudaMemsetAsync(ad1, 0, (size_t)NNODES * HH * sizeof(float));
    cudaMemsetAsync(as2, 0, (size_t)NNODES * sizeof(float));
    cudaMemsetAsync(ad2, 0, (size_t)NNODES * sizeof(float));
    cudaMemsetAsync(deg,  0, NNODES * sizeof(int));

    hist_kernel<<<(E + 255) / 256, 256>>>(dst, E, deg);
    scan_kernel<<<1, 1024>>>(deg, roff);
    scatter_kernel<<<(E + 255) / 256, 256>>>(src, dst, E, roff, deg, csr);

    // ---- layer 1 ----
    {
        dim3 grid(F1 / 128, (NNODES + 127) / 128);
        tf32_gemm_kernel<128, 128, 64, 32><<<grid, 256>>>(
            x, W1, h1h, asrc1, adst1, as1, ad1, NNODES, F1, FIN, HH);
    }
    gather1_kernel<<<(NNODES + 7) / 8, 256>>>(roff, csr, as1, ad1, h1h, b1, o1);

    // ---- layer 2 ----
    {
        dim3 grid(1, (NNODES + 127) / 128);
        tf32_gemm_kernel<128, 64, 64, 16><<<grid, 256>>>(
            o1, W2, h2h, asrc2, adst2, as2, ad2, NNODES, HD, F1, 1);
    }
    gather2_kernel<<<(NNODES + 7) / 8, 256>>>(roff, csr, as2, ad2, h2h, b2, out);
}

// round 17
// speedup vs baseline: 1.1819x; 1.0370x over previous
#include <cuda_runtime.h>
#include <cuda_fp16.h>
#include <math.h>

#define NNODES 50000
#define FIN    256
#define HH     4
#define HD     64
#define F1     (HH*HD)          // 256
#define EMAX   1600000
#define SLOPE  0.2f
#define FULLM  0xffffffffu

// ---------------- scratch (device globals) ----------------------------------
__device__ __half g_h1h[(size_t)NNODES * F1];    // 25.6 MB (fp16 h1)
__device__ float  g_o1[(size_t)NNODES * F1];     // 51.2 MB
__device__ __half g_h2h[(size_t)NNODES * HD];    // 6.4 MB (fp16 h2)
__device__ float  g_as1[NNODES * HH];
__device__ float  g_ad1[NNODES * HH];
__device__ float  g_as2[NNODES];
__device__ float  g_ad2[NNODES];
__device__ int    g_deg[NNODES];
__device__ int    g_roff[NNODES + 1];
__device__ int    g_csr_src[EMAX];               // 6.4 MB

// ---------------- tf32 helpers ----------------------------------------------
__device__ __forceinline__ unsigned f2tf(float f) {
    unsigned u;
    asm("cvt.rna.tf32.f32 %0, %1;" : "=r"(u) : "f"(f));
    return u;
}
__device__ __forceinline__ void mma_tf32(float* c, const unsigned* a, const unsigned* b) {
    asm volatile(
        "mma.sync.aligned.m16n8k8.row.col.f32.tf32.tf32.f32 "
        "{%0,%1,%2,%3}, {%4,%5,%6,%7}, {%8,%9}, {%0,%1,%2,%3};"
        : "+f"(c[0]), "+f"(c[1]), "+f"(c[2]), "+f"(c[3])
        : "r"(a[0]), "r"(a[1]), "r"(a[2]), "r"(a[3]), "r"(b[0]), "r"(b[1]));
}

// ------------- split-tf32 GEMM + fused alpha epilogue -----------------------
// TWOTERM=true drops the aH*bL correction (B effectively tf32): 2/3 the MMAs,
// no BsL staging. Error ~1-3e-4 relative — used for layer 1 only.
template<int BM, int BN, int WM, int WN, bool TWOTERM>
__global__ void tf32_gemm_kernel(const float* __restrict__ A,
                                 const float* __restrict__ B,
                                 __half* __restrict__ C16,
                                 const float* __restrict__ a_src,
                                 const float* __restrict__ a_dst,
                                 float* __restrict__ as_out,
                                 float* __restrict__ ad_out,
                                 int M, int N, int K, int heads)
{
    constexpr int BK = 16;
    constexpr int WARPS_M = BM / WM;
    constexpr int WARPS_N = BN / WN;
    constexpr int THREADS = WARPS_M * WARPS_N * 32;
    constexpr int MT = WM / 16;
    constexpr int NT = WN / 8;

    __shared__ unsigned AsH[BM][BK + 4];
    __shared__ unsigned AsL[BM][BK + 4];
    __shared__ unsigned BsH[BK][BN + 8];
    __shared__ unsigned BsL[TWOTERM ? 1 : BK][TWOTERM ? 1 : (BN + 8)];

    const int tid  = threadIdx.x;
    const int lane = tid & 31;
    const int wid  = tid >> 5;
    const int wm   = wid % WARPS_M;
    const int wn   = wid / WARPS_M;
    const int gid  = lane >> 2;
    const int tg   = lane & 3;
    const int row0 = blockIdx.y * BM;
    const int col0 = blockIdx.x * BN;

    float acc[MT][NT][4];
#pragma unroll
    for (int i = 0; i < MT; i++)
#pragma unroll
        for (int j = 0; j < NT; j++)
#pragma unroll
            for (int r = 0; r < 4; r++) acc[i][j][r] = 0.f;

    for (int k0 = 0; k0 < K; k0 += BK) {
#pragma unroll
        for (int i = tid; i < BM * (BK / 4); i += THREADS) {
            int m  = i / (BK / 4);
            int kq = (i % (BK / 4)) * 4;
            float4 v = make_float4(0.f, 0.f, 0.f, 0.f);
            if (row0 + m < M)
                v = *(const float4*)&A[(size_t)(row0 + m) * K + k0 + kq];
            float f[4] = {v.x, v.y, v.z, v.w};
#pragma unroll
            for (int j = 0; j < 4; j++) {
                unsigned h = f2tf(f[j]);
                AsH[m][kq + j] = h;
                AsL[m][kq + j] = f2tf(f[j] - __uint_as_float(h));
            }
        }
#pragma unroll
        for (int i = tid; i < BK * (BN / 4); i += THREADS) {
            int kk = i / (BN / 4);
            int nq = (i % (BN / 4)) * 4;
            float4 v = *(const float4*)&B[(size_t)(k0 + kk) * N + col0 + nq];
            float f[4] = {v.x, v.y, v.z, v.w};
#pragma unroll
            for (int j = 0; j < 4; j++) {
                unsigned h = f2tf(f[j]);
                BsH[kk][nq + j] = h;
                if (!TWOTERM)
                    BsL[kk][nq + j] = f2tf(f[j] - __uint_as_float(h));
            }
        }
        __syncthreads();

#pragma unroll
        for (int ks = 0; ks < BK / 8; ks++) {
            const int kb = ks * 8;
            unsigned aH[MT][4], aL[MT][4], bH[NT][2], bL[NT][2];
#pragma unroll
            for (int mt = 0; mt < MT; mt++) {
                int mr = wm * WM + mt * 16 + gid;
                aH[mt][0] = AsH[mr    ][kb + tg];
                aH[mt][1] = AsH[mr + 8][kb + tg];
                aH[mt][2] = AsH[mr    ][kb + tg + 4];
                aH[mt][3] = AsH[mr + 8][kb + tg + 4];
                aL[mt][0] = AsL[mr    ][kb + tg];
                aL[mt][1] = AsL[mr + 8][kb + tg];
                aL[mt][2] = AsL[mr    ][kb + tg + 4];
                aL[mt][3] = AsL[mr + 8][kb + tg + 4];
            }
#pragma unroll
            for (int nt = 0; nt < NT; nt++) {
                int nc = wn * WN + nt * 8 + gid;
                bH[nt][0] = BsH[kb + tg    ][nc];
                bH[nt][1] = BsH[kb + tg + 4][nc];
                if (!TWOTERM) {
                    bL[nt][0] = BsL[kb + tg    ][nc];
                    bL[nt][1] = BsL[kb + tg + 4][nc];
                }
            }
#pragma unroll
            for (int mt = 0; mt < MT; mt++)
#pragma unroll
                for (int nt = 0; nt < NT; nt++) {
                    mma_tf32(acc[mt][nt], aH[mt], bH[nt]);
                    if (!TWOTERM)
                        mma_tf32(acc[mt][nt], aH[mt], bL[nt]);
                    mma_tf32(acc[mt][nt], aL[mt], bH[nt]);
                }
        }
        __syncthreads();
    }

    // ---- epilogue: fp16 store + fused alpha partials ----
    const int head = (col0 + wn * WN) / 64;

#pragma unroll
    for (int mt = 0; mt < MT; mt++) {
        int m0 = row0 + wm * WM + mt * 16 + gid;
        float ps0 = 0.f, pd0 = 0.f, ps1 = 0.f, pd1 = 0.f;
#pragma unroll
        for (int nt = 0; nt < NT; nt++) {
            int nc = col0 + wn * WN + nt * 8 + tg * 2;
            float av0 = a_src[head * 64 + ((nc    ) & 63)];
            float av1 = a_src[head * 64 + ((nc + 1) & 63)];
            float dv0 = a_dst[head * 64 + ((nc    ) & 63)];
            float dv1 = a_dst[head * 64 + ((nc + 1) & 63)];
            ps0 = fmaf(acc[mt][nt][0], av0, fmaf(acc[mt][nt][1], av1, ps0));
            pd0 = fmaf(acc[mt][nt][0], dv0, fmaf(acc[mt][nt][1], dv1, pd0));
            ps1 = fmaf(acc[mt][nt][2], av0, fmaf(acc[mt][nt][3], av1, ps1));
            pd1 = fmaf(acc[mt][nt][2], dv0, fmaf(acc[mt][nt][3], dv1, pd1));
            if (m0 < M)
                *(__half2*)&C16[(size_t)m0 * N + nc] =
                    __floats2half2_rn(acc[mt][nt][0], acc[mt][nt][1]);
            if (m0 + 8 < M)
                *(__half2*)&C16[(size_t)(m0 + 8) * N + nc] =
                    __floats2half2_rn(acc[mt][nt][2], acc[mt][nt][3]);
        }
#pragma unroll
        for (int o = 1; o < 4; o <<= 1) {
            ps0 += __shfl_xor_sync(FULLM, ps0, o);
            pd0 += __shfl_xor_sync(FULLM, pd0, o);
            ps1 += __shfl_xor_sync(FULLM, ps1, o);
            pd1 += __shfl_xor_sync(FULLM, pd1, o);
        }
        if (tg == 0) {
            if (m0 < M) {
                atomicAdd(&as_out[(size_t)m0 * heads + head], ps0);
                atomicAdd(&ad_out[(size_t)m0 * heads + head], pd0);
            }
            if (m0 + 8 < M) {
                atomicAdd(&as_out[(size_t)(m0 + 8) * heads + head], ps1);
                atomicAdd(&ad_out[(size_t)(m0 + 8) * heads + head], pd1);
            }
        }
    }
}

// ---------------- CSR build -------------------------------------------------
__global__ void hist_kernel(const int* __restrict__ dst, int E, int* __restrict__ deg)
{
    int e = blockIdx.x * blockDim.x + threadIdx.x;
    if (e >= E) return;
    int d = dst[e];
    if ((unsigned)d < NNODES) atomicAdd(&deg[d], 1);
}

__global__ void scan_kernel(const int* __restrict__ deg, int* __restrict__ roff)
{
    __shared__ int part[1024];
    const int tid = threadIdx.x;
    const int CH = (NNODES + 1023) / 1024;
    const int base = tid * CH;
    int s = 0;
    for (int i = 0; i < CH; i++) {
        int idx = base + i;
        if (idx < NNODES) s += deg[idx];
    }
    part[tid] = s;
    __syncthreads();
    for (int off = 1; off < 1024; off <<= 1) {
        int v = 0;
        if (tid >= off) v = part[tid - off];
        __syncthreads();
        if (tid >= off) part[tid] += v;
        __syncthreads();
    }
    int run = (tid == 0) ? 0 : part[tid - 1];
    for (int i = 0; i < CH; i++) {
        int idx = base + i;
        if (idx < NNODES) { roff[idx] = run; run += deg[idx]; }
    }
    if (tid == 1023) roff[NNODES] = run;
}

// Reuses deg as the per-node slot counter (counts down); no fill array.
__global__ void scatter_kernel(const int* __restrict__ src, const int* __restrict__ dst,
                               int E, const int* __restrict__ roff,
                               int* __restrict__ deg, int* __restrict__ csr)
{
    int e = blockIdx.x * blockDim.x + threadIdx.x;
    if (e >= E) return;
    int d = dst[e], s = src[e];
    if ((unsigned)d >= NNODES || (unsigned)s >= NNODES) return;
    int old = atomicSub(&deg[d], 1);
    csr[roff[d] + old - 1] = s;
}

__device__ __forceinline__ float lexp(float e) {
    e = e > 0.f ? e : SLOPE * e;
    return __expf(e);
}

// -------- layer-1 single-pass softmax+gather (R13 proven, 4-wide) -----------
__global__ void gather1_kernel(const int* __restrict__ roff,
                               const int* __restrict__ csr,
                               const float* __restrict__ as_in,
                               const float* __restrict__ ad_in,
                               const __half* __restrict__ h16,
                               const float* __restrict__ bias,
                               float* __restrict__ out)
{
    int warp = (blockIdx.x * blockDim.x + threadIdx.x) >> 5;
    int lane = threadIdx.x & 31;
    if (warp >= NNODES) return;
    const int d = warp;
    const int beg = roff[d], end = roff[d + 1];
    const int hidx = lane >> 3;          // 8 lanes per head

    float4 ad4 = *(const float4*)(ad_in + (size_t)d * 4);

    float acc[8];
#pragma unroll
    for (int k = 0; k < 8; k++) acc[k] = 0.f;
    float4 ws = make_float4(0.f, 0.f, 0.f, 0.f);

#define ACCUM1(w, q)                                                    \
    {                                                                   \
        const __half2* hp = (const __half2*)&(q);                       \
        float2 f0 = __half22float2(hp[0]);                              \
        float2 f1 = __half22float2(hp[1]);                              \
        float2 f2 = __half22float2(hp[2]);                              \
        float2 f3 = __half22float2(hp[3]);                              \
        acc[0] = fmaf(w, f0.x, acc[0]); acc[1] = fmaf(w, f0.y, acc[1]); \
        acc[2] = fmaf(w, f1.x, acc[2]); acc[3] = fmaf(w, f1.y, acc[3]); \
        acc[4] = fmaf(w, f2.x, acc[4]); acc[5] = fmaf(w, f2.y, acc[5]); \
        acc[6] = fmaf(w, f3.x, acc[6]); acc[7] = fmaf(w, f3.y, acc[7]); \
    }
#define SELW(wx, wy, wz, ww) \
    ((hidx == 0) ? (wx) : (hidx == 1) ? (wy) : (hidx == 2) ? (wz) : (ww))
#define BCASTW(dstw, t)                                                 \
    {                                                                   \
        float _bx = __shfl_sync(FULLM, w4.x, (t));                      \
        float _by = __shfl_sync(FULLM, w4.y, (t));                      \
        float _bz = __shfl_sync(FULLM, w4.z, (t));                      \
        float _bw = __shfl_sync(FULLM, w4.w, (t));                      \
        dstw = SELW(_bx, _by, _bz, _bw);                                \
    }

    for (int j0 = beg; j0 < end; j0 += 32) {
        int cnt = min(32, end - j0);
        int my = 0;
        float4 w4 = make_float4(0.f, 0.f, 0.f, 0.f);
        if (lane < cnt) {
            my = csr[j0 + lane];
            float4 a = *(const float4*)(as_in + (size_t)my * 4);
            w4.x = lexp(a.x + ad4.x);
            w4.y = lexp(a.y + ad4.y);
            w4.z = lexp(a.z + ad4.z);
            w4.w = lexp(a.w + ad4.w);
            ws.x += w4.x; ws.y += w4.y; ws.z += w4.z; ws.w += w4.w;
        }
        int t = 0;
        for (; t + 3 < cnt; t += 4) {
            int s0 = __shfl_sync(FULLM, my, t);
            int s1 = __shfl_sync(FULLM, my, t + 1);
            int s2 = __shfl_sync(FULLM, my, t + 2);
            int s3 = __shfl_sync(FULLM, my, t + 3);
            uint4 q0 = *(const uint4*)(h16 + (size_t)s0 * F1 + lane * 8);
            uint4 q1 = *(const uint4*)(h16 + (size_t)s1 * F1 + lane * 8);
            uint4 q2 = *(const uint4*)(h16 + (size_t)s2 * F1 + lane * 8);
            uint4 q3 = *(const uint4*)(h16 + (size_t)s3 * F1 + lane * 8);
            float w0, w1, w2, w3;
            BCASTW(w0, t);
            BCASTW(w1, t + 1);
            BCASTW(w2, t + 2);
            BCASTW(w3, t + 3);
            ACCUM1(w0, q0); ACCUM1(w1, q1); ACCUM1(w2, q2); ACCUM1(w3, q3);
        }
        for (; t < cnt; t++) {
            int s0 = __shfl_sync(FULLM, my, t);
            uint4 q0 = *(const uint4*)(h16 + (size_t)s0 * F1 + lane * 8);
            float w0;
            BCASTW(w0, t);
            ACCUM1(w0, q0);
        }
    }
    {   // self loop
        float4 a = *(const float4*)(as_in + (size_t)d * 4);
        float sx = lexp(a.x + ad4.x), sy = lexp(a.y + ad4.y);
        float sz = lexp(a.z + ad4.z), sw = lexp(a.w + ad4.w);
        if (lane == 0) { ws.x += sx; ws.y += sy; ws.z += sz; ws.w += sw; }
        float w0 = SELW(sx, sy, sz, sw);
        uint4 q0 = *(const uint4*)(h16 + (size_t)d * F1 + lane * 8);
        ACCUM1(w0, q0);
    }
#undef ACCUM1
#undef BCASTW

#pragma unroll
    for (int o = 16; o > 0; o >>= 1) {
        ws.x += __shfl_xor_sync(FULLM, ws.x, o);
        ws.y += __shfl_xor_sync(FULLM, ws.y, o);
        ws.z += __shfl_xor_sync(FULLM, ws.z, o);
        ws.w += __shfl_xor_sync(FULLM, ws.w, o);
    }
    float inv = 1.f / (SELW(ws.x, ws.y, ws.z, ws.w) + 1e-16f);
#undef SELW

    size_t base = (size_t)d * F1 + lane * 8;
#pragma unroll
    for (int k = 0; k < 8; k++) {
        float v = acc[k] * inv + bias[lane * 8 + k];
        out[base + k] = v > 0.f ? v : expm1f(v);
    }
}

// -------- layer-2 single-pass softmax+gather (R13 proven, 4-wide) -----------
__global__ void gather2_kernel(const int* __restrict__ roff,
                               const int* __restrict__ csr,
                               const float* __restrict__ as_in,
                               const float* __restrict__ ad_in,
                               const __half* __restrict__ h16,
                               const float* __restrict__ bias,
                               float* __restrict__ out)
{
    int warp = (blockIdx.x * blockDim.x + threadIdx.x) >> 5;
    int lane = threadIdx.x & 31;
    if (warp >= NNODES) return;
    const int d = warp;
    const int beg = roff[d], end = roff[d + 1];

    float add = ad_in[d];
    float ws = 0.f;
    float2 acc = make_float2(0.f, 0.f);

    for (int j0 = beg; j0 < end; j0 += 32) {
        int cnt = min(32, end - j0);
        int my = 0;
        float wmy = 0.f;
        if (lane < cnt) {
            my = csr[j0 + lane];
            wmy = lexp(as_in[my] + add);
            ws += wmy;
        }
        int t = 0;
        for (; t + 3 < cnt; t += 4) {
            int s0 = __shfl_sync(FULLM, my, t);
            int s1 = __shfl_sync(FULLM, my, t + 1);
            int s2 = __shfl_sync(FULLM, my, t + 2);
            int s3 = __shfl_sync(FULLM, my, t + 3);
            __half2 v0 = *(const __half2*)(h16 + (size_t)s0 * HD + lane * 2);
            __half2 v1 = *(const __half2*)(h16 + (size_t)s1 * HD + lane * 2);
            __half2 v2 = *(const __half2*)(h16 + (size_t)s2 * HD + lane * 2);
            __half2 v3 = *(const __half2*)(h16 + (size_t)s3 * HD + lane * 2);
            float w0 = __shfl_sync(FULLM, wmy, t);
            float w1 = __shfl_sync(FULLM, wmy, t + 1);
            float w2 = __shfl_sync(FULLM, wmy, t + 2);
            float w3 = __shfl_sync(FULLM, wmy, t + 3);
            float2 f0 = __half22float2(v0), f1 = __half22float2(v1);
            float2 f2 = __half22float2(v2), f3 = __half22float2(v3);
            acc.x = fmaf(w0, f0.x, acc.x); acc.y = fmaf(w0, f0.y, acc.y);
            acc.x = fmaf(w1, f1.x, acc.x); acc.y = fmaf(w1, f1.y, acc.y);
            acc.x = fmaf(w2, f2.x, acc.x); acc.y = fmaf(w2, f2.y, acc.y);
            acc.x = fmaf(w3, f3.x, acc.x); acc.y = fmaf(w3, f3.y, acc.y);
        }
        for (; t < cnt; t++) {
            int s0 = __shfl_sync(FULLM, my, t);
            float w0 = __shfl_sync(FULLM, wmy, t);
            float2 u = __half22float2(*(const __half2*)(h16 + (size_t)s0 * HD + lane * 2));
            acc.x = fmaf(w0, u.x, acc.x); acc.y = fmaf(w0, u.y, acc.y);
        }
    }
    {   // self loop
        float w0 = lexp(as_in[d] + add);
        if (lane == 0) ws += w0;
        float2 u = __half22float2(*(const __half2*)(h16 + (size_t)d * HD + lane * 2));
        acc.x = fmaf(w0, u.x, acc.x); acc.y = fmaf(w0, u.y, acc.y);
    }

#pragma unroll
    for (int o = 16; o > 0; o >>= 1) ws += __shfl_xor_sync(FULLM, ws, o);
    float inv = 1.f / (ws + 1e-16f);

    out[(size_t)d * HD + lane * 2 + 0] = acc.x * inv + bias[lane * 2 + 0];
    out[(size_t)d * HD + lane * 2 + 1] = acc.y * inv + bias[lane * 2 + 1];
}

// ---------------- launch ----------------------------------------------------
extern "C" void kernel_launch(void* const* d_in, const int* in_sizes, int n_in,
                              void* d_out, int out_size)
{
    const float* x     = (const float*)d_in[0];
    const int*   ei    = (const int*)d_in[1];     // int32 (JAX x64 disabled)
    const float* W1    = (const float*)d_in[2];
    const float* asrc1 = (const float*)d_in[3];
    const float* adst1 = (const float*)d_in[4];
    const float* b1    = (const float*)d_in[5];
    const float* W2    = (const float*)d_in[6];
    const float* asrc2 = (const float*)d_in[7];
    const float* adst2 = (const float*)d_in[8];
    const float* b2    = (const float*)d_in[9];
    float*       out   = (float*)d_out;

    int E = in_sizes[1] / 2;
    if (E > EMAX) E = EMAX;
    const int* src = ei;
    const int* dst = ei + E;

    float *o1, *as1, *ad1, *as2, *ad2;
    __half *h1h, *h2h;
    int *deg, *roff, *csr;
    cudaGetSymbolAddress((void**)&h1h,  g_h1h);
    cudaGetSymbolAddress((void**)&o1,   g_o1);
    cudaGetSymbolAddress((void**)&h2h,  g_h2h);
    cudaGetSymbolAddress((void**)&as1,  g_as1);
    cudaGetSymbolAddress((void**)&ad1,  g_ad1);
    cudaGetSymbolAddress((void**)&as2,  g_as2);
    cudaGetSymbolAddress((void**)&ad2,  g_ad2);
    cudaGetSymbolAddress((void**)&deg,  g_deg);
    cudaGetSymbolAddress((void**)&roff, g_roff);
    cudaGetSymbolAddress((void**)&csr,  g_csr_src);

    cudaMemsetAsync(as1, 0, (size_t)NNODES * HH * sizeof(float));
    cudaMemsetAsync(ad1, 0, (size_t)NNODES * HH * sizeof(float));
    cudaMemsetAsync(as2, 0, (size_t)NNODES * sizeof(float));
    cudaMemsetAsync(ad2, 0, (size_t)NNODES * sizeof(float));
    cudaMemsetAsync(deg,  0, NNODES * sizeof(int));

    hist_kernel<<<(E + 255) / 256, 256>>>(dst, E, deg);
    scan_kernel<<<1, 1024>>>(deg, roff);
    scatter_kernel<<<(E + 255) / 256, 256>>>(src, dst, E, roff, deg, csr);

    // ---- layer 1 (2-term split-tf32) ----
    {
        dim3 grid(F1 / 128, (NNODES + 127) / 128);
        tf32_gemm_kernel<128, 128, 64, 32, true><<<grid, 256>>>(
            x, W1, h1h, asrc1, adst1, as1, ad1, NNODES, F1, FIN, HH);
    }
    gather1_kernel<<<(NNODES + 7) / 8, 256>>>(roff, csr, as1, ad1, h1h, b1, o1);

    // ---- layer 2 (3-term split-tf32) ----
    {
        dim3 grid(1, (NNODES + 127) / 128);
        tf32_gemm_kernel<128, 64, 64, 16, false><<<grid, 256>>>(
            o1, W2, h2h, asrc2, adst2, as2, ad2, NNODES, HD, F1, 1);
    }
    gather2_kernel<<<(NNODES + 7) / 8, 256>>>(roff, csr, as2, ad2, h2h, b2, out);
}